// round 6
// baseline (speedup 1.0000x reference)
#include <cuda_runtime.h>
#include <math.h>

#define NGRAPH 64
#define LNODES 2048
#define DDIM   128
#define SPLITK 4
#define CHUNK  (LNODES / SPLITK)   // 512
#define PAD    132

typedef unsigned long long u64;

// ---- packed f32x2 helpers (Blackwell; ptxas will not auto-fuse these) ----
__device__ __forceinline__ u64 f2_pack(float lo, float hi) {
    u64 r; asm("mov.b64 %0, {%1, %2};" : "=l"(r) : "f"(lo), "f"(hi)); return r;
}
__device__ __forceinline__ u64 f2_bcast(float v) { return f2_pack(v, v); }
__device__ __forceinline__ u64 f2_fma(u64 a, u64 b, u64 c) {
    u64 d; asm("fma.rn.f32x2 %0, %1, %2, %3;" : "=l"(d) : "l"(a), "l"(b), "l"(c)); return d;
}
__device__ __forceinline__ u64 f2_mul(u64 a, u64 b) {
    u64 d; asm("mul.rn.f32x2 %0, %1, %2;" : "=l"(d) : "l"(a), "l"(b)); return d;
}
__device__ __forceinline__ void f2_unpack(u64 v, float& lo, float& hi) {
    asm("mov.b64 {%0, %1}, %2;" : "=f"(lo), "=f"(hi) : "l"(v));
}

// Scratch: Gram partials + transposed squared weights.
__device__ float g_gram_part[NGRAPH * SPLITK * DDIM * DDIM];  // 16 MB
__device__ float g_w2t[DDIM * DDIM];                          // w2t[d*128+p] = w[p][d]^2

// ---------------------------------------------------------------------------
// Kernel 0: w2t[d][p] = w[p][d]^2
// ---------------------------------------------------------------------------
__global__ void k_w2t(const float* __restrict__ w) {
    int idx = blockIdx.x * 256 + threadIdx.x;   // 0..16383
    int d = idx >> 7, p = idx & 127;
    float v = w[p * DDIM + d];
    g_w2t[idx] = v * v;
}

// ---------------------------------------------------------------------------
// Kernel 1: Gram partials (128x128 = X_chunk^T X_chunk), f32x2-packed.
// ---------------------------------------------------------------------------
__global__ void __launch_bounds__(256) k_gram(const float* __restrict__ feats) {
    __shared__ float xs[32 * DDIM];             // 16 KB row-chunk
    int b  = blockIdx.x;
    int gj = b >> 2, ck = b & 3;
    const float4* X4 = (const float4*)(feats + ((size_t)gj * LNODES + (size_t)ck * CHUNK) * DDIM);

    int tid = threadIdx.x;
    int ty = tid >> 4, tx = tid & 15;

    u64 acc[8][4];
#pragma unroll
    for (int i = 0; i < 8; i++)
#pragma unroll
        for (int j = 0; j < 4; j++) acc[i][j] = 0ull;   // bit pattern of (0.f,0.f)

    float4* xs4 = (float4*)xs;
    for (int k0 = 0; k0 < CHUNK; k0 += 32) {
        __syncthreads();
#pragma unroll
        for (int t = 0; t < 4; t++)
            xs4[tid + t * 256] = X4[(size_t)k0 * 32 + tid + t * 256];
        __syncthreads();
#pragma unroll 8
        for (int k = 0; k < 32; k++) {
            float4 a0 = *(const float4*)&xs[k * DDIM + ty * 8];
            float4 a1 = *(const float4*)&xs[k * DDIM + ty * 8 + 4];
            ulonglong2 q0 = *(const ulonglong2*)&xs[k * DDIM + tx * 8];
            ulonglong2 q1 = *(const ulonglong2*)&xs[k * DDIM + tx * 8 + 4];
            float av[8] = {a0.x,a0.y,a0.z,a0.w,a1.x,a1.y,a1.z,a1.w};
            u64 bv[4] = {q0.x, q0.y, q1.x, q1.y};
#pragma unroll
            for (int i = 0; i < 8; i++) {
                u64 ai = f2_bcast(av[i]);
#pragma unroll
                for (int j = 0; j < 4; j++)
                    acc[i][j] = f2_fma(ai, bv[j], acc[i][j]);
            }
        }
    }
    float* outp = g_gram_part + (size_t)b * DDIM * DDIM;
#pragma unroll
    for (int i = 0; i < 8; i++) {
        ulonglong2 s0, s1;
        s0.x = acc[i][0]; s0.y = acc[i][1];
        s1.x = acc[i][2]; s1.y = acc[i][3];
        *(ulonglong2*)&outp[(ty * 8 + i) * DDIM + tx * 8]     = s0;
        *(ulonglong2*)&outp[(ty * 8 + i) * DDIM + tx * 8 + 4] = s1;
    }
}

// ---------------------------------------------------------------------------
// Kernel 2: fused main, f32x2-packed.
//   v2 = v1 @ Gram[partner]   (pass1, transposed via Gram symmetry)
//   out = (v1*v2)@W2T / max(sqrt((v1^2@W2T)*(v2^2@W2T)), eps)   (pass2, fused)
// ---------------------------------------------------------------------------
__global__ void __launch_bounds__(256) k_main(const float* __restrict__ feats,
                                              float* __restrict__ out) {
    extern __shared__ float sm[];
    float* mat = sm;                     // 128 x PAD : Gram then W2T
    float* v1t = sm + DDIM * PAD;        // 128 x PAD : V1^T  ([d][l])
    float* v2t = sm + 2 * DDIM * PAD;    // 128 x PAD : V2^T  ([d][l])

    int b    = blockIdx.x;               // 0..1023
    int gj   = b >> 4;
    int tile = b & 15;
    int row0 = gj * LNODES + tile * 128;
    int tid  = threadIdx.x;

    // ---- load V1 tile transposed into smem ----
    const float4* F4 = (const float4*)(feats + (size_t)row0 * DDIM);
#pragma unroll
    for (int t = 0; t < 16; t++) {
        int f  = tid + t * 256;
        int l  = f >> 5;
        int d4 = f & 31;
        float4 v = F4[f];
        v1t[(d4 * 4 + 0) * PAD + l] = v.x;
        v1t[(d4 * 4 + 1) * PAD + l] = v.y;
        v1t[(d4 * 4 + 2) * PAD + l] = v.z;
        v1t[(d4 * 4 + 3) * PAD + l] = v.w;
    }
    // ---- load partner Gram (sum of 4 split-K partials) ----
    {
        int partner = gj ^ 1;
        const float* gp = g_gram_part + (size_t)partner * SPLITK * DDIM * DDIM;
        for (int e = tid; e < DDIM * DDIM; e += 256) {
            float s = gp[e] + gp[e + DDIM * DDIM] + gp[e + 2 * DDIM * DDIM] + gp[e + 3 * DDIM * DDIM];
            mat[(e >> 7) * PAD + (e & 127)] = s;
        }
    }
    __syncthreads();

    int ty = tid >> 4, tx = tid & 15;

    // ---- pass1: V2^T[dout][l] = sum_din Gram[din][dout] * V1^T[din][l] ----
    {
        u64 acc[8][4];
#pragma unroll
        for (int i = 0; i < 8; i++)
#pragma unroll
            for (int j = 0; j < 4; j++) acc[i][j] = 0ull;

#pragma unroll 4
        for (int d = 0; d < DDIM; d++) {
            float4 a0 = *(const float4*)&mat[d * PAD + ty * 8];
            float4 a1 = *(const float4*)&mat[d * PAD + ty * 8 + 4];
            ulonglong2 q0 = *(const ulonglong2*)&v1t[d * PAD + tx * 8];
            ulonglong2 q1 = *(const ulonglong2*)&v1t[d * PAD + tx * 8 + 4];
            float av[8] = {a0.x,a0.y,a0.z,a0.w,a1.x,a1.y,a1.z,a1.w};
            u64 bv[4] = {q0.x, q0.y, q1.x, q1.y};
#pragma unroll
            for (int i = 0; i < 8; i++) {
                u64 ai = f2_bcast(av[i]);
#pragma unroll
                for (int j = 0; j < 4; j++)
                    acc[i][j] = f2_fma(ai, bv[j], acc[i][j]);
            }
        }
        __syncthreads();   // all reads of mat (Gram) + v1t for pass1 done
#pragma unroll
        for (int i = 0; i < 8; i++) {
            ulonglong2 s0, s1;
            s0.x = acc[i][0]; s0.y = acc[i][1];
            s1.x = acc[i][2]; s1.y = acc[i][3];
            *(ulonglong2*)&v2t[(ty * 8 + i) * PAD + tx * 8]     = s0;
            *(ulonglong2*)&v2t[(ty * 8 + i) * PAD + tx * 8 + 4] = s1;
        }
    }
    // ---- overwrite mat with W2T ----
    for (int e = tid; e < DDIM * DDIM; e += 256)
        mat[(e >> 7) * PAD + (e & 127)] = g_w2t[e];
    __syncthreads();

    // ---- pass2: fused triple GEMM (num, n1sq, n2sq), packed ----
    u64 aN[8][4], a1s[8][4], a2s[8][4];
#pragma unroll
    for (int i = 0; i < 8; i++)
#pragma unroll
        for (int j = 0; j < 4; j++) { aN[i][j] = 0ull; a1s[i][j] = 0ull; a2s[i][j] = 0ull; }

#pragma unroll 2
    for (int d = 0; d < DDIM; d++) {
        float4 x0 = *(const float4*)&v1t[d * PAD + ty * 8];
        float4 x1 = *(const float4*)&v1t[d * PAD + ty * 8 + 4];
        float4 y0 = *(const float4*)&v2t[d * PAD + ty * 8];
        float4 y1 = *(const float4*)&v2t[d * PAD + ty * 8 + 4];
        ulonglong2 q0 = *(const ulonglong2*)&mat[d * PAD + tx * 8];
        ulonglong2 q1 = *(const ulonglong2*)&mat[d * PAD + tx * 8 + 4];
        float xv[8] = {x0.x,x0.y,x0.z,x0.w,x1.x,x1.y,x1.z,x1.w};
        float yv[8] = {y0.x,y0.y,y0.z,y0.w,y1.x,y1.y,y1.z,y1.w};
        u64 bv[4] = {q0.x, q0.y, q1.x, q1.y};
#pragma unroll
        for (int i = 0; i < 8; i++) {
            u64 xp = f2_bcast(xv[i]);
            u64 yp = f2_bcast(yv[i]);
            u64 pn = f2_mul(xp, yp);
            u64 p1 = f2_mul(xp, xp);
            u64 p2 = f2_mul(yp, yp);
#pragma unroll
            for (int j = 0; j < 4; j++) {
                aN[i][j]  = f2_fma(pn, bv[j], aN[i][j]);
                a1s[i][j] = f2_fma(p1, bv[j], a1s[i][j]);
                a2s[i][j] = f2_fma(p2, bv[j], a2s[i][j]);
            }
        }
    }

    // ---- epilogue: out = num / max(sqrt(n1sq*n2sq), eps) ----
#pragma unroll
    for (int i = 0; i < 8; i++) {
        int row = row0 + ty * 8 + i;
        float r[8];
#pragma unroll
        for (int j = 0; j < 4; j++) {
            float n_lo, n_hi, s1_lo, s1_hi, s2_lo, s2_hi;
            f2_unpack(aN[i][j],  n_lo,  n_hi);
            f2_unpack(a1s[i][j], s1_lo, s1_hi);
            f2_unpack(a2s[i][j], s2_lo, s2_hi);
            float den0 = fmaxf(sqrtf(s1_lo * s2_lo), 1e-8f);
            float den1 = fmaxf(sqrtf(s1_hi * s2_hi), 1e-8f);
            r[2 * j]     = n_lo / den0;
            r[2 * j + 1] = n_hi / den1;
        }
        *(float4*)&out[(size_t)row * DDIM + tx * 8]     = make_float4(r[0], r[1], r[2], r[3]);
        *(float4*)&out[(size_t)row * DDIM + tx * 8 + 4] = make_float4(r[4], r[5], r[6], r[7]);
    }
}

// ---------------------------------------------------------------------------
extern "C" void kernel_launch(void* const* d_in, const int* in_sizes, int n_in,
                              void* d_out, int out_size) {
    const float* feats = nullptr;
    const float* mp_w  = nullptr;
    for (int i = 0; i < n_in; i++) {
        if (in_sizes[i] == 16777216)     feats = (const float*)d_in[i];
        else if (in_sizes[i] == 16384)   mp_w  = (const float*)d_in[i];
    }
    float* out = (float*)d_out;
    if (!feats || !mp_w || !out) return;

    const int smem_bytes = 3 * DDIM * PAD * (int)sizeof(float);   // 202752
    cudaFuncSetAttribute((const void*)k_main,
                         cudaFuncAttributeMaxDynamicSharedMemorySize, smem_bytes);

    k_w2t <<<64, 256>>>(mp_w);
    k_gram<<<NGRAPH * SPLITK, 256>>>(feats);
    k_main<<<NGRAPH * (LNODES / 128), 256, smem_bytes>>>(feats, out);
}

// round 10
// speedup vs baseline: 2.0384x; 2.0384x over previous
#include <cuda_runtime.h>
#include <cuda_bf16.h>
#include <math.h>
#include <stdint.h>

#define NGRAPH 64
#define LNODES 2048
#define DDIM   128
#define SPLITK 4
#define CHUNK  (LNODES / SPLITK)

// ---------------- global scratch ----------------
__device__ float g_gram_part[NGRAPH * SPLITK * DDIM * DDIM];   // 16 MB fp32 partials
__device__ __nv_bfloat16 g_gram_hi[NGRAPH * DDIM * DDIM];      // row-major n x k
__device__ __nv_bfloat16 g_gram_lo[NGRAPH * DDIM * DDIM];
__device__ __nv_bfloat16 g_w2_hi[DDIM * DDIM];                 // [p][d] = hi(w[p][d]^2)
__device__ __nv_bfloat16 g_w2_lo[DDIM * DDIM];

// ---------------- helpers ----------------
__device__ __forceinline__ void split2(float x, float y, uint32_t& hi, uint32_t& lo) {
    __nv_bfloat16 hx = __float2bfloat16_rn(x), hy = __float2bfloat16_rn(y);
    float rx = x - __bfloat162float(hx);
    float ry = y - __bfloat162float(hy);
    __nv_bfloat16 lx = __float2bfloat16_rn(rx), ly = __float2bfloat16_rn(ry);
    __nv_bfloat162 h = __halves2bfloat162(hx, hy);
    __nv_bfloat162 l = __halves2bfloat162(lx, ly);
    hi = *reinterpret_cast<uint32_t*>(&h);
    lo = *reinterpret_cast<uint32_t*>(&l);
}

// D += A(bf16x2 frags) * B(bf16x2 frags), fp32 accum. Standard m16n8k16 mapping.
__device__ __forceinline__ void mma_bf16(float d[4], const uint32_t a[4],
                                         uint32_t b0, uint32_t b1) {
    asm volatile(
        "mma.sync.aligned.m16n8k16.row.col.f32.bf16.bf16.f32 "
        "{%0,%1,%2,%3}, {%4,%5,%6,%7}, {%8,%9}, {%0,%1,%2,%3};"
        : "+f"(d[0]), "+f"(d[1]), "+f"(d[2]), "+f"(d[3])
        : "r"(a[0]), "r"(a[1]), "r"(a[2]), "r"(a[3]), "r"(b0), "r"(b1));
}

// ---------------------------------------------------------------------------
// k_w2: split w^2 -> bf16 hi/lo, row-major [p][d] (the .col B operand layout)
// ---------------------------------------------------------------------------
__global__ void k_w2(const float* __restrict__ w) {
    int idx = blockIdx.x * 256 + threadIdx.x;   // 0..16383
    float v = w[idx];
    float s = v * v;
    __nv_bfloat16 hi = __float2bfloat16_rn(s);
    __nv_bfloat16 lo = __float2bfloat16_rn(s - __bfloat162float(hi));
    g_w2_hi[idx] = hi;
    g_w2_lo[idx] = lo;
}

// ---------------------------------------------------------------------------
// k_gram: scalar fp32 Gram partials (proven R4 kernel, unchanged)
// ---------------------------------------------------------------------------
__global__ void __launch_bounds__(256) k_gram(const float* __restrict__ feats) {
    __shared__ float xs[32 * DDIM];
    int b  = blockIdx.x;
    int gj = b >> 2, ck = b & 3;
    const float4* X4 = (const float4*)(feats + ((size_t)gj * LNODES + (size_t)ck * CHUNK) * DDIM);
    int tid = threadIdx.x;
    int ty = tid >> 4, tx = tid & 15;
    float acc[8][8];
#pragma unroll
    for (int i = 0; i < 8; i++)
#pragma unroll
        for (int j = 0; j < 8; j++) acc[i][j] = 0.f;
    float4* xs4 = (float4*)xs;
    for (int k0 = 0; k0 < CHUNK; k0 += 32) {
        __syncthreads();
#pragma unroll
        for (int t = 0; t < 4; t++)
            xs4[tid + t * 256] = X4[(size_t)k0 * 32 + tid + t * 256];
        __syncthreads();
#pragma unroll 8
        for (int k = 0; k < 32; k++) {
            float4 a0 = *(const float4*)&xs[k * DDIM + ty * 8];
            float4 a1 = *(const float4*)&xs[k * DDIM + ty * 8 + 4];
            float4 b0 = *(const float4*)&xs[k * DDIM + tx * 8];
            float4 b1 = *(const float4*)&xs[k * DDIM + tx * 8 + 4];
            float av[8] = {a0.x,a0.y,a0.z,a0.w,a1.x,a1.y,a1.z,a1.w};
            float bv[8] = {b0.x,b0.y,b0.z,b0.w,b1.x,b1.y,b1.z,b1.w};
#pragma unroll
            for (int i = 0; i < 8; i++)
#pragma unroll
                for (int j = 0; j < 8; j++)
                    acc[i][j] = fmaf(av[i], bv[j], acc[i][j]);
        }
    }
    float* outp = g_gram_part + (size_t)b * DDIM * DDIM;
#pragma unroll
    for (int i = 0; i < 8; i++) {
        *(float4*)&outp[(ty * 8 + i) * DDIM + tx * 8]     = make_float4(acc[i][0], acc[i][1], acc[i][2], acc[i][3]);
        *(float4*)&outp[(ty * 8 + i) * DDIM + tx * 8 + 4] = make_float4(acc[i][4], acc[i][5], acc[i][6], acc[i][7]);
    }
}

// ---------------------------------------------------------------------------
// k_gsplit: sum split-K partials -> bf16 hi/lo row-major (Gram is symmetric)
// ---------------------------------------------------------------------------
__global__ void k_gsplit() {
    int g = blockIdx.x;
    const float* gp = g_gram_part + (size_t)g * SPLITK * DDIM * DDIM;
    __nv_bfloat16* bh = g_gram_hi + (size_t)g * DDIM * DDIM;
    __nv_bfloat16* bl = g_gram_lo + (size_t)g * DDIM * DDIM;
    for (int e = threadIdx.x; e < DDIM * DDIM; e += 256) {
        float s = gp[e] + gp[e + DDIM * DDIM] + gp[e + 2 * DDIM * DDIM] + gp[e + 3 * DDIM * DDIM];
        __nv_bfloat16 hi = __float2bfloat16_rn(s);
        __nv_bfloat16 lo = __float2bfloat16_rn(s - __bfloat162float(hi));
        bh[e] = hi;
        bl[e] = lo;
    }
}

// ---------------------------------------------------------------------------
// k_main: mma.sync bf16-split. 256 thr = 8 warps; warp w owns rows [16w,16w+16).
// SMEM: V1 f32[128][132] @0, V2 f32[128][132] @67584,
//       Bh bf16[128][136] @135168, Bl bf16[128][136] @169984  (204800 B)
// ---------------------------------------------------------------------------
#define V1_STR 132
#define B_STR  136
#define SMEM_MAIN 204800

__global__ void __launch_bounds__(256) k_main(const float* __restrict__ feats,
                                              float* __restrict__ out) {
    extern __shared__ char sm[];
    float* V1 = (float*)sm;
    float* V2 = (float*)(sm + 67584);
    __nv_bfloat16* Bh = (__nv_bfloat16*)(sm + 135168);
    __nv_bfloat16* Bl = (__nv_bfloat16*)(sm + 169984);

    int tid = threadIdx.x, wid = tid >> 5, lid = tid & 31;
    int grp = lid >> 2, qid = lid & 3;
    int b = blockIdx.x, gj = b >> 4, tile = b & 15;
    int row0 = gj * LNODES + tile * 128;
    int ra = wid * 16 + grp;              // smem-local A/C row (low half)

    // ---- load V1 tile (coalesced) ----
    const float4* F4 = (const float4*)(feats + (size_t)row0 * DDIM);
#pragma unroll
    for (int t = 0; t < 16; t++) {
        int i = tid + t * 256;            // 0..4095
        int r = i >> 5, c4 = i & 31;
        *(float4*)&V1[r * V1_STR + c4 * 4] = F4[i];
    }
    // ---- load partner Gram hi/lo -> B smem ----
    {
        const uint2* gh = (const uint2*)(g_gram_hi + (size_t)(gj ^ 1) * DDIM * DDIM);
        const uint2* gl = (const uint2*)(g_gram_lo + (size_t)(gj ^ 1) * DDIM * DDIM);
#pragma unroll
        for (int t = 0; t < 16; t++) {
            int i = tid + t * 256;        // 0..4095 uint2 (4 bf16 each)
            int r = i >> 5, s = i & 31;
            *(uint2*)&Bh[r * B_STR + s * 4] = gh[i];
            *(uint2*)&Bl[r * B_STR + s * 4] = gl[i];
        }
    }
    __syncthreads();

    // ================= pass1: V2 = V1 * Gram =================
    {
        float acc[16][4];
#pragma unroll
        for (int n = 0; n < 16; n++)
#pragma unroll
            for (int j = 0; j < 4; j++) acc[n][j] = 0.f;

#pragma unroll 1
        for (int kt = 0; kt < 8; kt++) {
            int k0 = kt * 16 + qid * 2;
            float2 a00 = *(const float2*)&V1[ra * V1_STR + k0];
            float2 a10 = *(const float2*)&V1[(ra + 8) * V1_STR + k0];
            float2 a01 = *(const float2*)&V1[ra * V1_STR + k0 + 8];
            float2 a11 = *(const float2*)&V1[(ra + 8) * V1_STR + k0 + 8];
            uint32_t ah[4], al[4];
            split2(a00.x, a00.y, ah[0], al[0]);
            split2(a10.x, a10.y, ah[1], al[1]);
            split2(a01.x, a01.y, ah[2], al[2]);
            split2(a11.x, a11.y, ah[3], al[3]);
            const __nv_bfloat16* bhp = &Bh[grp * B_STR + k0];
            const __nv_bfloat16* blp = &Bl[grp * B_STR + k0];
#pragma unroll
            for (int nt = 0; nt < 16; nt++) {
                uint32_t bh0 = *(const uint32_t*)(bhp);
                uint32_t bh1 = *(const uint32_t*)(bhp + 8);
                uint32_t bl0 = *(const uint32_t*)(blp);
                uint32_t bl1 = *(const uint32_t*)(blp + 8);
                bhp += 8 * B_STR; blp += 8 * B_STR;
                mma_bf16(acc[nt], ah, bh0, bh1);
                mma_bf16(acc[nt], ah, bl0, bl1);
                mma_bf16(acc[nt], al, bh0, bh1);
            }
        }
        // store V2 (C-frag mapping: rows grp/grp+8, cols 2q,2q+1 per ntile)
#pragma unroll
        for (int nt = 0; nt < 16; nt++) {
            int c = nt * 8 + qid * 2;
            *(float2*)&V2[ra * V1_STR + c]       = make_float2(acc[nt][0], acc[nt][1]);
            *(float2*)&V2[(ra + 8) * V1_STR + c] = make_float2(acc[nt][2], acc[nt][3]);
        }
    }
    __syncthreads();   // pass1 B reads + V2 writes complete

    // ---- swap B to W^2 hi/lo ----
    {
        const uint2* gh = (const uint2*)g_w2_hi;
        const uint2* gl = (const uint2*)g_w2_lo;
#pragma unroll
        for (int t = 0; t < 16; t++) {
            int i = tid + t * 256;
            int r = i >> 5, s = i & 31;
            *(uint2*)&Bh[r * B_STR + s * 4] = gh[i];
            *(uint2*)&Bl[r * B_STR + s * 4] = gl[i];
        }
    }
    __syncthreads();

    // ================= pass2: num / n1 / n2 GEMMs + fused epilogue =========
    for (int half = 0; half < 2; half++) {
        float aN[8][4], a1[8][4], a2[8][4];
#pragma unroll
        for (int n = 0; n < 8; n++)
#pragma unroll
            for (int j = 0; j < 4; j++) { aN[n][j] = 0.f; a1[n][j] = 0.f; a2[n][j] = 0.f; }

#pragma unroll 1
        for (int kt = 0; kt < 8; kt++) {
            int k0 = kt * 16 + qid * 2;
            float2 x00 = *(const float2*)&V1[ra * V1_STR + k0];
            float2 x10 = *(const float2*)&V1[(ra + 8) * V1_STR + k0];
            float2 x01 = *(const float2*)&V1[ra * V1_STR + k0 + 8];
            float2 x11 = *(const float2*)&V1[(ra + 8) * V1_STR + k0 + 8];
            float2 y00 = *(const float2*)&V2[ra * V1_STR + k0];
            float2 y10 = *(const float2*)&V2[(ra + 8) * V1_STR + k0];
            float2 y01 = *(const float2*)&V2[ra * V1_STR + k0 + 8];
            float2 y11 = *(const float2*)&V2[(ra + 8) * V1_STR + k0 + 8];

            uint32_t nh[4], nl[4], s1h[4], s1l[4], s2h[4], s2l[4];
            split2(x00.x * y00.x, x00.y * y00.y, nh[0], nl[0]);
            split2(x10.x * y10.x, x10.y * y10.y, nh[1], nl[1]);
            split2(x01.x * y01.x, x01.y * y01.y, nh[2], nl[2]);
            split2(x11.x * y11.x, x11.y * y11.y, nh[3], nl[3]);
            split2(x00.x * x00.x, x00.y * x00.y, s1h[0], s1l[0]);
            split2(x10.x * x10.x, x10.y * x10.y, s1h[1], s1l[1]);
            split2(x01.x * x01.x, x01.y * x01.y, s1h[2], s1l[2]);
            split2(x11.x * x11.x, x11.y * x11.y, s1h[3], s1l[3]);
            split2(y00.x * y00.x, y00.y * y00.y, s2h[0], s2l[0]);
            split2(y10.x * y10.x, y10.y * y10.y, s2h[1], s2l[1]);
            split2(y01.x * y01.x, y01.y * y01.y, s2h[2], s2l[2]);
            split2(y11.x * y11.x, y11.y * y11.y, s2h[3], s2l[3]);

            const __nv_bfloat16* bhp = &Bh[(half * 64 + grp) * B_STR + k0];
            const __nv_bfloat16* blp = &Bl[(half * 64 + grp) * B_STR + k0];
#pragma unroll
            for (int nt = 0; nt < 8; nt++) {
                uint32_t bh0 = *(const uint32_t*)(bhp);
                uint32_t bh1 = *(const uint32_t*)(bhp + 8);
                uint32_t bl0 = *(const uint32_t*)(blp);
                uint32_t bl1 = *(const uint32_t*)(blp + 8);
                bhp += 8 * B_STR; blp += 8 * B_STR;
                mma_bf16(aN[nt], nh, bh0, bh1);
                mma_bf16(aN[nt], nh, bl0, bl1);
                mma_bf16(aN[nt], nl, bh0, bh1);
                mma_bf16(a1[nt], s1h, bh0, bh1);
                mma_bf16(a1[nt], s1h, bl0, bl1);
                mma_bf16(a1[nt], s1l, bh0, bh1);
                mma_bf16(a2[nt], s2h, bh0, bh1);
                mma_bf16(a2[nt], s2h, bl0, bl1);
                mma_bf16(a2[nt], s2l, bh0, bh1);
            }
        }
        // ---- epilogue for this half ----
        size_t orow0 = (size_t)(row0 + ra) * DDIM;
        size_t orow1 = (size_t)(row0 + ra + 8) * DDIM;
#pragma unroll
        for (int nt = 0; nt < 8; nt++) {
            int col = half * 64 + nt * 8 + qid * 2;
            float d0 = fmaxf(sqrtf(a1[nt][0] * a2[nt][0]), 1e-8f);
            float d1 = fmaxf(sqrtf(a1[nt][1] * a2[nt][1]), 1e-8f);
            float d2 = fmaxf(sqrtf(a1[nt][2] * a2[nt][2]), 1e-8f);
            float d3 = fmaxf(sqrtf(a1[nt][3] * a2[nt][3]), 1e-8f);
            *(float2*)&out[orow0 + col] = make_float2(aN[nt][0] / d0, aN[nt][1] / d1);
            *(float2*)&out[orow1 + col] = make_float2(aN[nt][2] / d2, aN[nt][3] / d3);
        }
    }
}

// ---------------------------------------------------------------------------
extern "C" void kernel_launch(void* const* d_in, const int* in_sizes, int n_in,
                              void* d_out, int out_size) {
    const float* feats = nullptr;
    const float* mp_w  = nullptr;
    for (int i = 0; i < n_in; i++) {
        if (in_sizes[i] == 16777216)     feats = (const float*)d_in[i];
        else if (in_sizes[i] == 16384)   mp_w  = (const float*)d_in[i];
    }
    float* out = (float*)d_out;
    if (!feats || !mp_w || !out) return;

    cudaFuncSetAttribute((const void*)k_main,
                         cudaFuncAttributeMaxDynamicSharedMemorySize, SMEM_MAIN);

    k_w2    <<<64, 256>>>(mp_w);
    k_gram  <<<NGRAPH * SPLITK, 256>>>(feats);
    k_gsplit<<<NGRAPH, 256>>>();
    k_main  <<<NGRAPH * (LNODES / 128), 256, SMEM_MAIN>>>(feats, out);
}